// round 15
// baseline (speedup 1.0000x reference)
#include <cuda_runtime.h>
#include <cuda_fp16.h>
#include <cstdint>

#define B_   8
#define N_   64
#define E_   256
#define L_   128
#define PH    136      // half pitch for MMA operand tiles

// ---------------- device globals ----------------
__device__ float  g_A[512*128];
__device__ float  g_C[512*128];
__device__ __half g_eenc[2048*128];
__device__ float  g_gve[2*8*128];
__device__ float  g_gvn[2*8*128];
__device__ __half g_Wh[11*128*128];       // pre-transposed [n][k] fp16 weights
__device__ int    g_csr_off[8*65];
__device__ int    g_csr_edge[8*256];

__device__ __forceinline__ float lrelu(float v){ return v > 0.f ? v : 0.01f*v; }
__device__ __forceinline__ uint32_t smem_u32(const void* p){
    uint32_t a;
    asm("{ .reg .u64 t; cvta.to.shared.u64 t, %1; cvt.u32.u64 %0, t; }" : "=r"(a) : "l"(p));
    return a;
}

#define LDSM4(D, addr) \
    asm volatile("ldmatrix.sync.aligned.m8n8.x4.shared.b16 {%0,%1,%2,%3}, [%4];" \
        : "=r"((D)[0]),"=r"((D)[1]),"=r"((D)[2]),"=r"((D)[3]) : "r"(addr))

#define MMA_H(C, A, b0, b1) \
    asm volatile("mma.sync.aligned.m16n8k16.row.col.f32.f16.f16.f32 " \
        "{%0,%1,%2,%3}, {%4,%5,%6,%7}, {%8,%9}, {%0,%1,%2,%3};" \
        : "+f"((C)[0]),"+f"((C)[1]),"+f"((C)[2]),"+f"((C)[3]) \
        : "r"((A)[0]),"r"((A)[1]),"r"((A)[2]),"r"((A)[3]), "r"(b0),"r"(b1))

#define CPA_COMMIT() asm volatile("cp.async.commit_group;" ::: "memory")
#define CPA_WAIT(n)  asm volatile("cp.async.wait_group %0;" :: "n"(n) : "memory")

// async copy of a 128x128 fp16 tile into pitched smem (512 threads)
__device__ __forceinline__ void cpa_tile(uint32_t sbase, const __half* __restrict__ src, int tid){
    #pragma unroll
    for (int i = tid; i < 2048; i += 512){
        int r = i >> 4, c = i & 15;
        asm volatile("cp.async.cg.shared.global [%0], [%1], 16;"
            :: "r"(sbase + (uint32_t)(r*PH + c*8)*2u), "l"(src + r*128 + c*8) : "memory");
    }
}

// ---------------- sync tile copies (used by k_prep) ----------------
template<int NT>
__device__ __forceinline__ void copy_f2h(__half* dst, const float* __restrict__ src, int tid){
    #pragma unroll
    for (int i = tid; i < 2048; i += NT){
        int r = i >> 4, c = i & 15;
        float4 v0 = *(const float4*)&src[r*128 + c*8];
        float4 v1 = *(const float4*)&src[r*128 + c*8 + 4];
        union { uint4 u; __half2 h[4]; } pk;
        pk.h[0] = __floats2half2_rn(v0.x, v0.y);
        pk.h[1] = __floats2half2_rn(v0.z, v0.w);
        pk.h[2] = __floats2half2_rn(v1.x, v1.y);
        pk.h[3] = __floats2half2_rn(v1.z, v1.w);
        *(uint4*)&dst[r*PH + c*8] = pk.u;
    }
}

// ---------------- gemm cores ----------------
__device__ __forceinline__ void g128h(float c[2][4][4], const uint32_t aA[2], const uint32_t aB[2]){
    #pragma unroll
    for (int k = 0; k < 8; k++){
        uint32_t A0[4], A1[4];
        LDSM4(A0, aA[0] + (uint32_t)k*32u);
        LDSM4(A1, aA[1] + (uint32_t)k*32u);
        #pragma unroll
        for (int p = 0; p < 2; p++){
            uint32_t Bv[4];
            LDSM4(Bv, aB[p] + (uint32_t)k*32u);
            MMA_H(c[0][2*p],   A0, Bv[0], Bv[1]);
            MMA_H(c[0][2*p+1], A0, Bv[2], Bv[3]);
            MMA_H(c[1][2*p],   A1, Bv[0], Bv[1]);
            MMA_H(c[1][2*p+1], A1, Bv[2], Bv[3]);
        }
    }
}
__device__ __forceinline__ void g64h(float c[2][2][4], const uint32_t aA[2], uint32_t aB){
    #pragma unroll
    for (int k = 0; k < 8; k++){
        uint32_t A0[4], A1[4], Bv[4];
        LDSM4(A0, aA[0] + (uint32_t)k*32u);
        LDSM4(A1, aA[1] + (uint32_t)k*32u);
        LDSM4(Bv, aB + (uint32_t)k*32u);
        MMA_H(c[0][0], A0, Bv[0], Bv[1]);
        MMA_H(c[0][1], A0, Bv[2], Bv[3]);
        MMA_H(c[1][0], A1, Bv[0], Bv[1]);
        MMA_H(c[1][1], A1, Bv[2], Bv[3]);
    }
}
__device__ __forceinline__ void g64h_dual(float ch[2][2][4], float cd[2][2][4],
                                          const uint32_t aA[2], uint32_t aB, uint32_t aB2){
    #pragma unroll
    for (int k = 0; k < 8; k++){
        uint32_t A0[4], A1[4], Bv[4], Bw[4];
        LDSM4(A0, aA[0] + (uint32_t)k*32u);
        LDSM4(A1, aA[1] + (uint32_t)k*32u);
        LDSM4(Bv, aB + (uint32_t)k*32u);
        LDSM4(Bw, aB2 + (uint32_t)k*32u);
        MMA_H(ch[0][0], A0, Bv[0], Bv[1]);
        MMA_H(ch[0][1], A0, Bv[2], Bv[3]);
        MMA_H(ch[1][0], A1, Bv[0], Bv[1]);
        MMA_H(ch[1][1], A1, Bv[2], Bv[3]);
        MMA_H(cd[0][0], A0, Bw[0], Bw[1]);
        MMA_H(cd[0][1], A0, Bw[2], Bw[3]);
        MMA_H(cd[1][0], A1, Bw[0], Bw[1]);
        MMA_H(cd[1][1], A1, Bw[2], Bw[3]);
    }
}
__device__ __forceinline__ void g128h8(float c[2][8][4], const uint32_t aA[2], const uint32_t aB[4]){
    #pragma unroll
    for (int k = 0; k < 8; k++){
        uint32_t A0[4], A1[4];
        LDSM4(A0, aA[0] + (uint32_t)k*32u);
        LDSM4(A1, aA[1] + (uint32_t)k*32u);
        #pragma unroll
        for (int p = 0; p < 4; p++){
            uint32_t Bv[4];
            LDSM4(Bv, aB[p] + (uint32_t)k*32u);
            MMA_H(c[0][2*p],   A0, Bv[0], Bv[1]);
            MMA_H(c[0][2*p+1], A0, Bv[2], Bv[3]);
            MMA_H(c[1][2*p],   A1, Bv[0], Bv[1]);
            MMA_H(c[1][2*p+1], A1, Bv[2], Bv[3]);
        }
    }
}

// ---------------- merged prep kernel (256 threads) — unchanged from R11 ----------------
#define SMEM_PREP (34816*2)
__global__ void k_prep(const float* __restrict__ x, const float* __restrict__ Wne,
                       const float* __restrict__ u, const float* __restrict__ Wg,
                       const float* __restrict__ bg,
                       const float* __restrict__ Wenc, const float* __restrict__ benc,
                       const float* __restrict__ ea,
                       const float* __restrict__ Wedge, const float* __restrict__ be,
                       const float* __restrict__ Wnode, const float* __restrict__ bn,
                       const int* __restrict__ edge_index){
    __shared__ float sbuf[64*129];
    extern __shared__ char dyn[];
    int blk = blockIdx.x, tid = threadIdx.x;
    if (blk < 22){
        int mat = blk >> 1, k0 = (blk & 1)*64;
        int m = mat - 1, s = m / 5, t = m % 5;
        #pragma unroll
        for (int i = tid; i < 8192; i += 256){
            int kk = i >> 7, n = i & 127;
            int k = k0 + kk;
            float v;
            if (mat == 0) v = Wenc[k*L_ + n];
            else if (t == 0) v = Wedge[(s*512 +       k)*L_ + n];
            else if (t == 1) v = Wedge[(s*512 + 128 + k)*L_ + n];
            else if (t == 2) v = Wedge[(s*512 + 256 + k)*L_ + n];
            else if (t == 3) v = Wnode[(s*384 +       k)*L_ + n];
            else             v = Wnode[(s*384 + 128 + k)*L_ + n];
            sbuf[kk*129 + n] = v;
        }
        __syncthreads();
        #pragma unroll
        for (int j = tid; j < 8192; j += 256){
            int n = j >> 6, kk = j & 63;
            g_Wh[mat*16384 + n*128 + k0 + kk] = __float2half_rn(sbuf[kk*129 + n]);
        }
    } else if (blk < 86){
        float (*xs)[128] = (float(*)[128])sbuf;
        const float* W1 = Wne;
        const float* W2 = Wne + 16384;
        int r0 = (blk - 22)*8;
        for (int i = tid; i < 1024; i += 256) xs[i>>7][i&127] = x[(r0 + (i>>7))*128 + (i&127)];
        __syncthreads();
        int c = tid & 127, rq = tid >> 7;
        float a1[4] = {0,0,0,0}, a2[4] = {0,0,0,0};
        #pragma unroll 8
        for (int k = 0; k < 128; k++){
            float w1 = W1[k*128 + c], w2 = W2[k*128 + c];
            #pragma unroll
            for (int j = 0; j < 4; j++){
                float xv = xs[rq*4 + j][k];
                a1[j] += xv*w1; a2[j] += xv*w2;
            }
        }
        #pragma unroll
        for (int j = 0; j < 4; j++){
            g_A[(r0 + rq*4 + j)*128 + c] = a1[j];
            g_C[(r0 + rq*4 + j)*128 + c] = a2[j];
        }
    } else if (blk < 94){
        int* cnt = (int*)sbuf;
        int* off = cnt + 64;
        int b = blk - 86;
        if (tid < 64) cnt[tid] = 0;
        __syncthreads();
        int dv = edge_index[b*512 + 256 + tid];
        atomicAdd(&cnt[dv], 1);
        __syncthreads();
        if (tid == 0){
            int o = 0;
            for (int n = 0; n < 64; n++){ off[n] = o; o += cnt[n]; }
            off[64] = o;
            for (int n = 0; n <= 64; n++) g_csr_off[b*65 + n] = off[n];
            for (int n = 0; n < 64; n++) cnt[n] = off[n];
        }
        __syncthreads();
        int pos = atomicAdd(&cnt[dv], 1);
        g_csr_edge[b*256 + pos] = tid;
    } else if (blk < 126){
        float* red = sbuf;
        float* sgg = sbuf + 256;
        int id = blk - 94;
        int b = id & 7, s = (id >> 3) & 1, kind = id >> 4;
        int c = tid & 127, hf = tid >> 7;
        float p = 0.f;
        #pragma unroll 16
        for (int k = 0; k < 64; k++)
            p += u[b*128 + hf*64 + k] * Wg[(hf*64 + k)*128 + c];
        red[tid] = p;
        __syncthreads();
        if (tid < 128) sgg[tid] = lrelu(bg[tid] + red[tid] + red[tid + 128]);
        __syncthreads();
        const float* W = (kind == 0) ? (Wedge + (s*512 + 384)*L_)
                                     : (Wnode + (s*384 + 256)*L_);
        float q = 0.f;
        #pragma unroll 16
        for (int k = 0; k < 64; k++)
            q += sgg[hf*64 + k] * W[(hf*64 + k)*128 + c];
        red[tid] = q;
        __syncthreads();
        if (tid < 128){
            float acc = ((kind == 0) ? be[s*128 + tid] : bn[s*128 + tid])
                      + red[tid] + red[tid + 128];
            if (kind == 0) g_gve[(s*8 + b)*128 + tid] = acc;
            else           g_gvn[(s*8 + b)*128 + tid] = acc;
        }
    } else {
        __half* s_xh = (__half*)dyn;
        __half* s_wh = (__half*)(dyn + 34816);
        int eb = blk - 126;
        int row0 = eb*128;
        int wid = tid >> 5, lane = tid & 31;
        int trow = lane >> 2, tcol2 = (lane & 3)*2;
        int wr = (wid & 3)*32, wn = (wid >> 2)*64;

        copy_f2h<256>(s_xh, ea + (long)row0*128, tid);
        #pragma unroll
        for (int i = tid; i < 16384; i += 256){
            int k = i >> 7, n = i & 127;
            s_wh[n*PH + k] = __float2half_rn(Wenc[k*128 + n]);
        }
        __syncthreads();

        uint32_t sb = smem_u32(dyn);
        int l15 = lane & 15, kA = ((lane>>4)&1)*8, kB = ((lane>>3)&1)*8;
        uint32_t aA[2], aB[4];
        #pragma unroll
        for (int m = 0; m < 2; m++)
            aA[m] = sb + (uint32_t)(((wr + m*16 + l15)*PH + kA))*2u;
        #pragma unroll
        for (int p = 0; p < 4; p++){
            int rn = wn + p*16 + ((lane>>4)<<3) + (lane&7);
            aB[p] = sb + 34816u + (uint32_t)((rn*PH + kB))*2u;
        }
        float c8[2][8][4] = {};
        g128h8(c8, aA, aB);

        #pragma unroll
        for (int m = 0; m < 2; m++){
            int rA = row0 + wr + m*16 + trow;
            #pragma unroll
            for (int nt = 0; nt < 8; nt++){
                int col = wn + nt*8 + tcol2;
                float2 bi = *(const float2*)&benc[col];
                *(__half2*)&g_eenc[(long)rA*128 + col] =
                    __floats2half2_rn(lrelu(c8[m][nt][0]+bi.x), lrelu(c8[m][nt][1]+bi.y));
                *(__half2*)&g_eenc[(long)(rA+8)*128 + col] =
                    __floats2half2_rn(lrelu(c8[m][nt][2]+bi.x), lrelu(c8[m][nt][3]+bi.y));
            }
        }
    }
}

// ---------------- fused per-(b,d) kernel (R11 math; cp.async triple-buffer weights) ----------------
#define OB_EE  0         // 69632
#define OB_W   69632     // 34816  buffer W0
#define OB_W2  104448    // 34816  buffer W1
#define OB_W3  139264    // 34816  buffer W2
#define OB_H   174080    // 17408
#define OB_HS  191488    // 17408 (s_ag aliases; hs dead by agg time)
#define OB_HD  208896    // 17408
#define OB_GV  226304    // 1536
#define OB_WSC 227840    // 512
#define OB_SC  228352    // 1024
#define OB_INT 229376    // src 1024 + dst 1024
#define SMEM_FUSED 231424

__global__ __launch_bounds__(512, 1) void k_fused(
    const float* __restrict__ spdist, const int* __restrict__ edge_index,
    const float* __restrict__ w3, const float* __restrict__ bias,
    const float* __restrict__ Wsc, const float* __restrict__ bsc,
    float* __restrict__ out)
{
    extern __shared__ char smc[];
    __half* s_ee  = (__half*)(smc + OB_EE);
    __half* s_h   = (__half*)(smc + OB_H);
    __half* s_hs  = (__half*)(smc + OB_HS);
    __half* s_hd  = (__half*)(smc + OB_HD);
    __half* s_ag  = (__half*)(smc + OB_HS);
    float*  s_gv  = (float*)(smc + OB_GV);
    float*  s_wsc = (float*)(smc + OB_WSC);
    float*  s_sc  = (float*)(smc + OB_SC);
    int*    s_src = (int*)(smc + OB_INT);
    int*    s_dst = s_src + 256;

    int tid = threadIdx.x, wid = tid >> 5, lane = tid & 31;
    int bd = blockIdx.x, b = bd >> 6, d = bd & 63;
    int trow = lane >> 2, tcol2 = (lane & 3)*2;
    int wr  = (wid & 3)*32, wn  = (wid >> 2)*32;
    int wr2 = (wid & 1)*32, wn2 = (wid >> 1)*16;

    uint32_t sb = smem_u32(smc);
    uint32_t bW0 = sb + OB_W, bW1 = sb + OB_W2, bW2 = sb + OB_W3;

    // ---- async prefetch: s0 weights (group A), ee tile (group B) ----
    cpa_tile(bW0, g_Wh + 2*16384, tid);   // Ws0
    cpa_tile(bW1, g_Wh + 3*16384, tid);   // Wd0
    cpa_tile(bW2, g_Wh + 1*16384, tid);   // Wedge0
    CPA_COMMIT();                          // group A
    {
        const __half* esrc = g_eenc + (long)b*256*128;
        #pragma unroll
        for (int i = tid; i < 4096; i += 512){
            int r = i >> 4, c = i & 15;
            asm volatile("cp.async.cg.shared.global [%0], [%1], 16;"
                :: "r"(sb + OB_EE + (uint32_t)(r*PH + c*8)*2u), "l"(esrc + r*128 + c*8) : "memory");
        }
    }
    CPA_COMMIT();                          // group B

    // ---- regular init loads (overlap the async copies) ----
    if (tid < 256){
        s_src[tid] = edge_index[b*512 + tid];
        s_dst[tid] = edge_index[b*512 + 256 + tid];
        s_sc[tid] = bsc[0];
    }
    if (tid < 128) s_wsc[tid] = Wsc[tid];
    if (tid < 128)       s_gv[tid] = g_gve[b*128 + tid];
    else if (tid < 256)  s_gv[tid] = g_gvn[b*128 + (tid-128)];
    else if (tid < 384)  s_gv[tid] = g_gve[(8 + b)*128 + (tid-256)];

    // h0 = lrelu(A + C + sp*w3 + bias) -> fp16
    #pragma unroll
    for (int i = tid; i < 2048; i += 512){
        int row = i >> 5, c4 = i & 31;
        float sp = spdist[(b*64 + d)*64 + row];
        float4 a  = *(const float4*)&g_A[(b*64 + row)*128 + c4*4];
        float4 cc = *(const float4*)&g_C[bd*128 + c4*4];
        float4 w  = *(const float4*)&w3[c4*4];
        float4 bi = *(const float4*)&bias[c4*4];
        union { uint2 u; __half2 h[2]; } pk;
        pk.h[0] = __floats2half2_rn(lrelu(a.x + cc.x + sp*w.x + bi.x),
                                    lrelu(a.y + cc.y + sp*w.y + bi.y));
        pk.h[1] = __floats2half2_rn(lrelu(a.z + cc.z + sp*w.z + bi.z),
                                    lrelu(a.w + cc.w + sp*w.w + bi.w));
        *(uint2*)&s_h[row*PH + c4*4] = pk.u;
    }

    // fragment addresses (A operands fixed; B bases chosen per step)
    int l15 = lane & 15, kA = ((lane>>4)&1)*8, kB = ((lane>>3)&1)*8;
    uint32_t aAe[2][2], aAh[2], aAg[2];
    #pragma unroll
    for (int m = 0; m < 2; m++){
        uint32_t ro = (uint32_t)(((wr + m*16 + l15)*PH + kA))*2u;
        aAe[0][m] = sb + OB_EE + ro;
        aAe[1][m] = sb + OB_EE + 34816u + ro;
        aAh[m] = sb + OB_H  + (uint32_t)(((wr2 + m*16 + l15)*PH + kA))*2u;
        aAg[m] = sb + OB_HS + (uint32_t)(((wr2 + m*16 + l15)*PH + kA))*2u;
    }
    uint32_t off128[2], off64;
    #pragma unroll
    for (int p = 0; p < 2; p++){
        int rn = wn + p*16 + ((lane>>4)<<3) + (lane&7);
        off128[p] = (uint32_t)((rn*PH + kB))*2u;
    }
    {
        int rn = wn2 + ((lane>>4)<<3) + (lane&7);
        off64 = (uint32_t)((rn*PH + kB))*2u;
    }

    for (int s = 0; s < 2; s++){
        int gvo = s*256;
        uint32_t aBs, aBs2, aBe[2];
        if (s == 0){
            aBs = bW0 + off64; aBs2 = bW1 + off64;
            aBe[0] = bW2 + off128[0]; aBe[1] = bW2 + off128[1];
        } else {
            aBs = bW2 + off64; aBs2 = bW0 + off64;
            aBe[0] = bW1 + off128[0]; aBe[1] = bW1 + off128[1];
        }
        if (s == 0) CPA_WAIT(1); else CPA_WAIT(0);
        __syncthreads();

        // ---- hs/hd dual gemm ----
        {
            float ch[2][2][4] = {}, cd[2][2][4] = {};
            g64h_dual(ch, cd, aAh, aBs, aBs2);
            #pragma unroll
            for (int m = 0; m < 2; m++){
                int rA = wr2 + m*16 + trow;
                #pragma unroll
                for (int nt = 0; nt < 2; nt++){
                    int col = wn2 + nt*8 + tcol2;
                    *(__half2*)&s_hs[rA*PH + col]     = __floats2half2_rn(ch[m][nt][0], ch[m][nt][1]);
                    *(__half2*)&s_hs[(rA+8)*PH + col] = __floats2half2_rn(ch[m][nt][2], ch[m][nt][3]);
                    *(__half2*)&s_hd[rA*PH + col]     = __floats2half2_rn(cd[m][nt][0], cd[m][nt][1]);
                    *(__half2*)&s_hd[(rA+8)*PH + col] = __floats2half2_rn(cd[m][nt][2], cd[m][nt][3]);
                }
            }
        }
        CPA_WAIT(0);                       // ee tile (B) complete (no-op at s1)
        __syncthreads();                   // hs/hd + ee visible; W0/W1 reads done
        if (s == 0){
            cpa_tile(bW0, g_Wh + 4*16384, tid);   // Wn1 -> W0 (Ws0 dead)
            cpa_tile(bW1, g_Wh + 5*16384, tid);   // Wn2 -> W1 (Wd0 dead)
            CPA_COMMIT();                  // group C
        }

        // ---- edge tiles (R11 gather epilogues, verbatim) ----
        for (int et = 0; et < 2; et++){
            int e0 = et*128;
            float c8[2][4][4] = {};
            g128h(c8, aAe[et], aBe);
            if (s == 0){
                __syncthreads();           // A-reads done before in-place write
                #pragma unroll
                for (int m = 0; m < 2; m++){
                    int lrA = wr + m*16 + trow, lrB = lrA + 8;
                    int sA = s_src[e0+lrA], dA = s_dst[e0+lrA];
                    int sB = s_src[e0+lrB], dB = s_dst[e0+lrB];
                    #pragma unroll
                    for (int nt = 0; nt < 4; nt++){
                        int col = wn + nt*8 + tcol2;
                        float2 gv = *(float2*)&s_gv[gvo + col];
                        float2 h1 = __half22float2(*(__half2*)&s_hs[sA*PH + col]);
                        float2 d1 = __half22float2(*(__half2*)&s_hd[dA*PH + col]);
                        float2 p1 = __half22float2(*(__half2*)&s_ee[(e0+lrA)*PH + col]);
                        *(__half2*)&s_ee[(e0+lrA)*PH + col] = __floats2half2_rn(
                            p1.x + lrelu(c8[m][nt][0] + h1.x + d1.x + gv.x),
                            p1.y + lrelu(c8[m][nt][1] + h1.y + d1.y + gv.y));
                        float2 h2 = __half22float2(*(__half2*)&s_hs[sB*PH + col]);
                        float2 d2 = __half22float2(*(__half2*)&s_hd[dB*PH + col]);
                        float2 p2 = __half22float2(*(__half2*)&s_ee[(e0+lrB)*PH + col]);
                        *(__half2*)&s_ee[(e0+lrB)*PH + col] = __floats2half2_rn(
                            p2.x + lrelu(c8[m][nt][2] + h2.x + d2.x + gv.x),
                            p2.y + lrelu(c8[m][nt][3] + h2.y + d2.y + gv.y));
                    }
                }
            } else {
                float part[2][2] = {{0.f,0.f},{0.f,0.f}};
                #pragma unroll
                for (int m = 0; m < 2; m++){
                    int lrA = wr + m*16 + trow, lrB = lrA + 8;
                    int sA = s_src[e0+lrA], dA = s_dst[e0+lrA];
                    int sB = s_src[e0+lrB], dB = s_dst[e0+lrB];
                    #pragma unroll
                    for (int nt = 0; nt < 4; nt++){
                        int col = wn + nt*8 + tcol2;
                        float2 gv = *(float2*)&s_gv[gvo + col];
                        float2 wv = *(float2*)&s_wsc[col];
                        float2 h1 = __half22float2(*(__half2*)&s_hs[sA*PH + col]);
                        float2 d1 = __half22float2(*(__half2*)&s_hd[dA*PH + col]);
                        float2 p1 = __half22float2(*(__half2*)&s_ee[(e0+lrA)*PH + col]);
                        float o1x = p1.x + lrelu(c8[m][nt][0] + h1.x + d1.x + gv.x);
                        float o1y = p1.y + lrelu(c8[m][nt][1] + h1.y + d1.y + gv.y);
                        part[m][0] += o1x*wv.x + o1y*wv.y;
                        float2 h2 = __half22float2(*(__half2*)&s_hs[sB*PH + col]);
                        float2 d2 = __half22float2(*(__half2*)&s_hd[dB*PH + col]);
                        float2 p2 = __half22float2(*(__half2*)&s_ee[(e0+lrB)*PH + col]);
                        float o2x = p2.x + lrelu(c8[m][nt][2] + h2.x + d2.x + gv.x);
                        float o2y = p2.y + lrelu(c8[m][nt][3] + h2.y + d2.y + gv.y);
                        part[m][1] += o2x*wv.x + o2y*wv.y;
                    }
                }
                #pragma unroll
                for (int m = 0; m < 2; m++)
                    #pragma unroll
                    for (int i = 0; i < 2; i++){
                        float v = part[m][i];
                        v += __shfl_xor_sync(0xFFFFFFFFu, v, 1);
                        v += __shfl_xor_sync(0xFFFFFFFFu, v, 2);
                        if ((lane & 3) == 0)
                            atomicAdd(&s_sc[e0 + wr + m*16 + trow + i*8], v);
                    }
            }
        }
        __syncthreads();                   // tiles final / scores done; W2(s0)/W1(s1) reads done

        if (s == 0){
            cpa_tile(bW2, g_Wh + 7*16384, tid);   // Ws1 -> W2 (Wedge0 dead)
            CPA_COMMIT();                  // group D

            // ---- agg (CSR from global; uint4 smem reads) -> s_ag ----
            {
                int n = tid >> 3, cg = tid & 7;
                float acc[16];
                #pragma unroll
                for (int q = 0; q < 16; q++) acc[q] = 0.f;
                int j0 = g_csr_off[b*65 + n], j1 = g_csr_off[b*65 + n + 1];
                for (int j = j0; j < j1; j++){
                    int e = g_csr_edge[b*256 + j];
                    const uint4* p = (const uint4*)&s_ee[e*PH + cg*16];
                    uint4 v0 = p[0], v1 = p[1];
                    const __half2* h0 = (const __half2*)&v0;
                    const __half2* h1 = (const __half2*)&v1;
                    #pragma unroll
                    for (int q = 0; q < 4; q++){
                        float2 a0 = __half22float2(h0[q]);
                        float2 a1 = __half22float2(h1[q]);
                        acc[2*q]   += a0.x; acc[2*q+1] += a0.y;
                        acc[8+2*q] += a1.x; acc[8+2*q+1] += a1.y;
                    }
                }
                union { uint4 u[2]; __half2 h[8]; } pk;
                #pragma unroll
                for (int q = 0; q < 8; q++) pk.h[q] = __floats2half2_rn(acc[2*q], acc[2*q+1]);
                *(uint4*)&s_ag[n*PH + cg*16]     = pk.u[0];
                *(uint4*)&s_ag[n*PH + cg*16 + 8] = pk.u[1];
            }
            CPA_WAIT(1);                   // Wn1/Wn2 (C) done; Ws1 (D) may pend
            __syncthreads();

            float cn[2][2][4] = {};
            g64h(cn, aAh, bW0 + off64);    // h   @ Wn1 (W0)
            g64h(cn, aAg, bW1 + off64);    // agg @ Wn2 (W1)
            __syncthreads();               // node-gemm W0/W1 reads done
            cpa_tile(bW0, g_Wh + 8*16384, tid);   // Wd1    -> W0
            cpa_tile(bW1, g_Wh + 6*16384, tid);   // Wedge1 -> W1
            CPA_COMMIT();                  // group E
            #pragma unroll
            for (int m = 0; m < 2; m++){
                int rA = wr2 + m*16 + trow;
                #pragma unroll
                for (int nt = 0; nt < 2; nt++){
                    int col = wn2 + nt*8 + tcol2;
                    float2 gv = *(float2*)&s_gv[128 + col];
                    float2 h1 = __half22float2(*(__half2*)&s_h[rA*PH + col]);
                    float2 h2 = __half22float2(*(__half2*)&s_h[(rA+8)*PH + col]);
                    *(__half2*)&s_h[rA*PH + col] = __floats2half2_rn(
                        h1.x + lrelu(cn[m][nt][0] + gv.x),
                        h1.y + lrelu(cn[m][nt][1] + gv.y));
                    *(__half2*)&s_h[(rA+8)*PH + col] = __floats2half2_rn(
                        h2.x + lrelu(cn[m][nt][2] + gv.x),
                        h2.y + lrelu(cn[m][nt][3] + gv.y));
                }
            }
            // s1's top CPA_WAIT(0)+__syncthreads covers h visibility + groups D/E
        } else {
            if (tid < 256)
                out[b*(E_*N_) + tid*N_ + d] = s_sc[tid];
        }
    }
}

// ---------------- launch ----------------
extern "C" void kernel_launch(void* const* d_in, const int* in_sizes, int n_in,
                              void* d_out, int out_size){
    const float* x          = (const float*)d_in[0];
    const float* edge_attr  = (const float*)d_in[1];
    const float* u          = (const float*)d_in[2];
    const float* spdist     = (const float*)d_in[3];
    const int*   edge_index = (const int*)  d_in[4];
    const float* W_node_enc = (const float*)d_in[5];
    const float* b_node_enc = (const float*)d_in[6];
    const float* W_edge_enc = (const float*)d_in[7];
    const float* b_edge_enc = (const float*)d_in[8];
    const float* W_glob_enc = (const float*)d_in[9];
    const float* b_glob_enc = (const float*)d_in[10];
    const float* W_edge_upd = (const float*)d_in[11];
    const float* b_edge_upd = (const float*)d_in[12];
    const float* W_node_upd = (const float*)d_in[13];
    const float* b_node_upd = (const float*)d_in[14];
    const float* W_score    = (const float*)d_in[15];
    const float* b_score    = (const float*)d_in[16];
    float* out = (float*)d_out;

    cudaFuncSetAttribute(k_prep,  cudaFuncAttributeMaxDynamicSharedMemorySize, SMEM_PREP);
    cudaFuncSetAttribute(k_fused, cudaFuncAttributeMaxDynamicSharedMemorySize, SMEM_FUSED);

    k_prep <<<142, 256, SMEM_PREP>>>(x, W_node_enc, u, W_glob_enc, b_glob_enc,
                                     W_edge_enc, b_edge_enc, edge_attr,
                                     W_edge_upd, b_edge_upd, W_node_upd, b_node_upd,
                                     edge_index);
    k_fused<<<512, 512, SMEM_FUSED>>>(spdist, edge_index,
                                      W_node_enc + 256*128, b_node_enc,
                                      W_score, b_score, out);
}

// round 16
// speedup vs baseline: 1.0026x; 1.0026x over previous
#include <cuda_runtime.h>
#include <cuda_fp16.h>
#include <cstdint>

#define B_   8
#define N_   64
#define E_   256
#define L_   128
#define PH    136      // half pitch for MMA operand tiles

// ---------------- device globals ----------------
__device__ float  g_A[512*128];
__device__ float  g_C[512*128];
__device__ __half g_eenc[2048*128];
__device__ float  g_gve[2*8*128];
__device__ float  g_gvn[2*8*128];
__device__ __half g_Wh[11*128*128];       // pre-transposed [n][k] fp16 weights
__device__ int    g_csr_off[8*65];
__device__ int    g_csr_edge[8*256];

__device__ __forceinline__ float lrelu(float v){ return v > 0.f ? v : 0.01f*v; }
__device__ __forceinline__ uint32_t smem_u32(const void* p){
    uint32_t a;
    asm("{ .reg .u64 t; cvta.to.shared.u64 t, %1; cvt.u32.u64 %0, t; }" : "=r"(a) : "l"(p));
    return a;
}

#define LDSM4(D, addr) \
    asm volatile("ldmatrix.sync.aligned.m8n8.x4.shared.b16 {%0,%1,%2,%3}, [%4];" \
        : "=r"((D)[0]),"=r"((D)[1]),"=r"((D)[2]),"=r"((D)[3]) : "r"(addr))

#define MMA_H(C, A, b0, b1) \
    asm volatile("mma.sync.aligned.m16n8k16.row.col.f32.f16.f16.f32 " \
        "{%0,%1,%2,%3}, {%4,%5,%6,%7}, {%8,%9}, {%0,%1,%2,%3};" \
        : "+f"((C)[0]),"+f"((C)[1]),"+f"((C)[2]),"+f"((C)[3]) \
        : "r"((A)[0]),"r"((A)[1]),"r"((A)[2]),"r"((A)[3]), "r"(b0),"r"(b1))

#define CPA_COMMIT() asm volatile("cp.async.commit_group;" ::: "memory")
#define CPA_WAIT0()  asm volatile("cp.async.wait_group 0;" ::: "memory")

// async copy of a 128x128 fp16 tile into pitched smem (512 threads)
__device__ __forceinline__ void cpa_tile(uint32_t sbase, const __half* __restrict__ src, int tid){
    #pragma unroll
    for (int i = tid; i < 2048; i += 512){
        int r = i >> 4, c = i & 15;
        asm volatile("cp.async.cg.shared.global [%0], [%1], 16;"
            :: "r"(sbase + (uint32_t)(r*PH + c*8)*2u), "l"(src + r*128 + c*8) : "memory");
    }
}

// ---------------- tile copies ----------------
template<int NT>
__device__ __forceinline__ void copy_hh(__half* dst, const __half* __restrict__ src, int tid){
    #pragma unroll
    for (int i = tid; i < 2048; i += NT){
        int r = i >> 4, c = i & 15;
        *(uint4*)&dst[r*PH + c*8] = *(const uint4*)&src[r*128 + c*8];
    }
}
template<int NT>
__device__ __forceinline__ void copy_f2h(__half* dst, const float* __restrict__ src, int tid){
    #pragma unroll
    for (int i = tid; i < 2048; i += NT){
        int r = i >> 4, c = i & 15;
        float4 v0 = *(const float4*)&src[r*128 + c*8];
        float4 v1 = *(const float4*)&src[r*128 + c*8 + 4];
        union { uint4 u; __half2 h[4]; } pk;
        pk.h[0] = __floats2half2_rn(v0.x, v0.y);
        pk.h[1] = __floats2half2_rn(v0.z, v0.w);
        pk.h[2] = __floats2half2_rn(v1.x, v1.y);
        pk.h[3] = __floats2half2_rn(v1.z, v1.w);
        *(uint4*)&dst[r*PH + c*8] = pk.u;
    }
}

// ---------------- gemm cores ----------------
__device__ __forceinline__ void g128h(float c[2][4][4], const uint32_t aA[2], const uint32_t aB[2]){
    #pragma unroll
    for (int k = 0; k < 8; k++){
        uint32_t A0[4], A1[4];
        LDSM4(A0, aA[0] + (uint32_t)k*32u);
        LDSM4(A1, aA[1] + (uint32_t)k*32u);
        #pragma unroll
        for (int p = 0; p < 2; p++){
            uint32_t Bv[4];
            LDSM4(Bv, aB[p] + (uint32_t)k*32u);
            MMA_H(c[0][2*p],   A0, Bv[0], Bv[1]);
            MMA_H(c[0][2*p+1], A0, Bv[2], Bv[3]);
            MMA_H(c[1][2*p],   A1, Bv[0], Bv[1]);
            MMA_H(c[1][2*p+1], A1, Bv[2], Bv[3]);
        }
    }
}
__device__ __forceinline__ void g64h(float c[2][2][4], const uint32_t aA[2], uint32_t aB){
    #pragma unroll
    for (int k = 0; k < 8; k++){
        uint32_t A0[4], A1[4], Bv[4];
        LDSM4(A0, aA[0] + (uint32_t)k*32u);
        LDSM4(A1, aA[1] + (uint32_t)k*32u);
        LDSM4(Bv, aB + (uint32_t)k*32u);
        MMA_H(c[0][0], A0, Bv[0], Bv[1]);
        MMA_H(c[0][1], A0, Bv[2], Bv[3]);
        MMA_H(c[1][0], A1, Bv[0], Bv[1]);
        MMA_H(c[1][1], A1, Bv[2], Bv[3]);
    }
}
__device__ __forceinline__ void g64h_dual(float ch[2][2][4], float cd[2][2][4],
                                          const uint32_t aA[2], uint32_t aB, uint32_t aB2){
    #pragma unroll
    for (int k = 0; k < 8; k++){
        uint32_t A0[4], A1[4], Bv[4], Bw[4];
        LDSM4(A0, aA[0] + (uint32_t)k*32u);
        LDSM4(A1, aA[1] + (uint32_t)k*32u);
        LDSM4(Bv, aB + (uint32_t)k*32u);
        LDSM4(Bw, aB2 + (uint32_t)k*32u);
        MMA_H(ch[0][0], A0, Bv[0], Bv[1]);
        MMA_H(ch[0][1], A0, Bv[2], Bv[3]);
        MMA_H(ch[1][0], A1, Bv[0], Bv[1]);
        MMA_H(ch[1][1], A1, Bv[2], Bv[3]);
        MMA_H(cd[0][0], A0, Bw[0], Bw[1]);
        MMA_H(cd[0][1], A0, Bw[2], Bw[3]);
        MMA_H(cd[1][0], A1, Bw[0], Bw[1]);
        MMA_H(cd[1][1], A1, Bw[2], Bw[3]);
    }
}

// ---------------- merged prep kernel (512 threads) ----------------
#define SMEM_PREP (34816*2)
__global__ __launch_bounds__(512, 1) void k_prep(
                       const float* __restrict__ x, const float* __restrict__ Wne,
                       const float* __restrict__ u, const float* __restrict__ Wg,
                       const float* __restrict__ bg,
                       const float* __restrict__ Wenc, const float* __restrict__ benc,
                       const float* __restrict__ ea,
                       const float* __restrict__ Wedge, const float* __restrict__ be,
                       const float* __restrict__ Wnode, const float* __restrict__ bn,
                       const int* __restrict__ edge_index){
    __shared__ float sbuf[64*129];
    extern __shared__ char dyn[];
    int blk = blockIdx.x, tid = threadIdx.x;
    if (blk < 22){
        int mat = blk >> 1, k0 = (blk & 1)*64;
        int m = mat - 1, s = m / 5, t = m % 5;
        #pragma unroll
        for (int i = tid; i < 8192; i += 512){
            int kk = i >> 7, n = i & 127;
            int k = k0 + kk;
            float v;
            if (mat == 0) v = Wenc[k*L_ + n];
            else if (t == 0) v = Wedge[(s*512 +       k)*L_ + n];
            else if (t == 1) v = Wedge[(s*512 + 128 + k)*L_ + n];
            else if (t == 2) v = Wedge[(s*512 + 256 + k)*L_ + n];
            else if (t == 3) v = Wnode[(s*384 +       k)*L_ + n];
            else             v = Wnode[(s*384 + 128 + k)*L_ + n];
            sbuf[kk*129 + n] = v;
        }
        __syncthreads();
        #pragma unroll
        for (int j = tid; j < 8192; j += 512){
            int n = j >> 6, kk = j & 63;
            g_Wh[mat*16384 + n*128 + k0 + kk] = __float2half_rn(sbuf[kk*129 + n]);
        }
    } else if (blk < 86){
        float (*xs)[128] = (float(*)[128])sbuf;
        const float* W1 = Wne;
        const float* W2 = Wne + 16384;
        int r0 = (blk - 22)*8;
        for (int i = tid; i < 1024; i += 512) xs[i>>7][i&127] = x[(r0 + (i>>7))*128 + (i&127)];
        __syncthreads();
        int c = tid & 127, rq = tid >> 7;       // rq in 0..3, 2 rows each
        float a1[2] = {0,0}, a2[2] = {0,0};
        #pragma unroll 8
        for (int k = 0; k < 128; k++){
            float w1 = W1[k*128 + c], w2 = W2[k*128 + c];
            #pragma unroll
            for (int j = 0; j < 2; j++){
                float xv = xs[rq*2 + j][k];
                a1[j] += xv*w1; a2[j] += xv*w2;
            }
        }
        #pragma unroll
        for (int j = 0; j < 2; j++){
            g_A[(r0 + rq*2 + j)*128 + c] = a1[j];
            g_C[(r0 + rq*2 + j)*128 + c] = a2[j];
        }
    } else if (blk < 94){
        int* cnt = (int*)sbuf;
        int* off = cnt + 64;
        int b = blk - 86;
        if (tid < 64) cnt[tid] = 0;
        __syncthreads();
        int dv = -1;
        if (tid < 256){
            dv = edge_index[b*512 + 256 + tid];
            atomicAdd(&cnt[dv], 1);
        }
        __syncthreads();
        if (tid == 0){
            int o = 0;
            for (int n = 0; n < 64; n++){ off[n] = o; o += cnt[n]; }
            off[64] = o;
            for (int n = 0; n <= 64; n++) g_csr_off[b*65 + n] = off[n];
            for (int n = 0; n < 64; n++) cnt[n] = off[n];
        }
        __syncthreads();
        if (tid < 256){
            int pos = atomicAdd(&cnt[dv], 1);
            g_csr_edge[b*256 + pos] = tid;
        }
    } else if (blk < 126){
        float* red = sbuf;
        float* sgg = sbuf + 256;
        int id = blk - 94;
        int b = id & 7, s = (id >> 3) & 1, kind = id >> 4;
        int c = tid & 127, hf = (tid >> 7) & 1;
        if (tid < 256){
            float p = 0.f;
            #pragma unroll 16
            for (int k = 0; k < 64; k++)
                p += u[b*128 + hf*64 + k] * Wg[(hf*64 + k)*128 + c];
            red[tid] = p;
        }
        __syncthreads();
        if (tid < 128) sgg[tid] = lrelu(bg[tid] + red[tid] + red[tid + 128]);
        __syncthreads();
        if (tid < 256){
            const float* W = (kind == 0) ? (Wedge + (s*512 + 384)*L_)
                                         : (Wnode + (s*384 + 256)*L_);
            float q = 0.f;
            #pragma unroll 16
            for (int k = 0; k < 64; k++)
                q += sgg[hf*64 + k] * W[(hf*64 + k)*128 + c];
            red[tid] = q;
        }
        __syncthreads();
        if (tid < 128){
            float acc = ((kind == 0) ? be[s*128 + tid] : bn[s*128 + tid])
                      + red[tid] + red[tid + 128];
            if (kind == 0) g_gve[(s*8 + b)*128 + tid] = acc;
            else           g_gvn[(s*8 + b)*128 + tid] = acc;
        }
    } else {
        // edge encoder block: 16 warps, 128x128 gemm
        __half* s_xh = (__half*)dyn;
        __half* s_wh = (__half*)(dyn + 34816);
        int eb = blk - 126;
        int row0 = eb*128;
        int wid = tid >> 5, lane = tid & 31;
        int trow = lane >> 2, tcol2 = (lane & 3)*2;
        int wr = (wid & 3)*32, wn = (wid >> 2)*32;

        copy_f2h<512>(s_xh, ea + (long)row0*128, tid);
        #pragma unroll
        for (int i = tid; i < 16384; i += 512){
            int k = i >> 7, n = i & 127;
            s_wh[n*PH + k] = __float2half_rn(Wenc[k*128 + n]);
        }
        __syncthreads();

        uint32_t sb = smem_u32(dyn);
        int l15 = lane & 15, kA = ((lane>>4)&1)*8, kB = ((lane>>3)&1)*8;
        uint32_t aA[2], aB[2];
        #pragma unroll
        for (int m = 0; m < 2; m++)
            aA[m] = sb + (uint32_t)(((wr + m*16 + l15)*PH + kA))*2u;
        #pragma unroll
        for (int p = 0; p < 2; p++){
            int rn = wn + p*16 + ((lane>>4)<<3) + (lane&7);
            aB[p] = sb + 34816u + (uint32_t)((rn*PH + kB))*2u;
        }
        float c8[2][4][4] = {};
        g128h(c8, aA, aB);

        #pragma unroll
        for (int m = 0; m < 2; m++){
            int rA = row0 + wr + m*16 + trow;
            #pragma unroll
            for (int nt = 0; nt < 4; nt++){
                int col = wn + nt*8 + tcol2;
                float2 bi = *(const float2*)&benc[col];
                *(__half2*)&g_eenc[(long)rA*128 + col] =
                    __floats2half2_rn(lrelu(c8[m][nt][0]+bi.x), lrelu(c8[m][nt][1]+bi.y));
                *(__half2*)&g_eenc[(long)(rA+8)*128 + col] =
                    __floats2half2_rn(lrelu(c8[m][nt][2]+bi.x), lrelu(c8[m][nt][3]+bi.y));
            }
        }
    }
}

// ---------------- fused per-(b,d) kernel (R11 verbatim + init cp.async) ----------------
#define OB_EE  0         // 69632
#define OB_W   69632     // 34816
#define OB_W2  104448    // 34816
#define OB_H   139264    // 17408
#define OB_HS  156672    // 17408 (s_ag aliases; hs dead by agg time)
#define OB_HD  174080    // 17408
#define OB_GV  191488    // 2048
#define OB_WSC 193536    // 512
#define OB_SC  194048    // 1024
#define OB_INT 195072    // 3336
#define SMEM_FUSED 198408

__global__ __launch_bounds__(512, 1) void k_fused(
    const float* __restrict__ spdist, const int* __restrict__ edge_index,
    const float* __restrict__ w3, const float* __restrict__ bias,
    const float* __restrict__ Wsc, const float* __restrict__ bsc,
    float* __restrict__ out)
{
    extern __shared__ char smc[];
    __half* s_ee  = (__half*)(smc + OB_EE);
    __half* s_h   = (__half*)(smc + OB_H);
    __half* s_hs  = (__half*)(smc + OB_HS);
    __half* s_hd  = (__half*)(smc + OB_HD);
    __half* s_ag  = (__half*)(smc + OB_HS);
    float*  s_gv  = (float*)(smc + OB_GV);
    float*  s_wsc = (float*)(smc + OB_WSC);
    float*  s_sc  = (float*)(smc + OB_SC);
    int*    s_src = (int*)(smc + OB_INT);
    int*    s_dst = s_src + 256;
    int*    s_coff = s_dst + 256;
    int*    s_cedge = s_coff + 66;
    __half* s_w   = (__half*)(smc + OB_W);
    __half* s_w2  = (__half*)(smc + OB_W2);

    int tid = threadIdx.x, wid = tid >> 5, lane = tid & 31;
    int bd = blockIdx.x, b = bd >> 6, d = bd & 63;
    int trow = lane >> 2, tcol2 = (lane & 3)*2;
    int wr  = (wid & 3)*32, wn  = (wid >> 2)*32;
    int wr2 = (wid & 1)*32, wn2 = (wid >> 1)*16;

    uint32_t sb = smem_u32(smc);

    // ---- init cp.async: Ws0/Wd0 + ee tile (single group, waited at s0 top) ----
    cpa_tile(sb + OB_W,  g_Wh + 2*16384, tid);   // Ws0
    cpa_tile(sb + OB_W2, g_Wh + 3*16384, tid);   // Wd0
    {
        const __half* esrc = g_eenc + (long)b*256*128;
        #pragma unroll
        for (int i = tid; i < 4096; i += 512){
            int r = i >> 4, c = i & 15;
            asm volatile("cp.async.cg.shared.global [%0], [%1], 16;"
                :: "r"(sb + OB_EE + (uint32_t)(r*PH + c*8)*2u), "l"(esrc + r*128 + c*8) : "memory");
        }
    }
    CPA_COMMIT();

    // ---- init (overlaps the async copies) ----
    if (tid < 256){
        s_src[tid] = edge_index[b*512 + tid];
        s_dst[tid] = edge_index[b*512 + 256 + tid];
        s_cedge[tid] = g_csr_edge[b*256 + tid];
        s_sc[tid] = bsc[0];
    }
    if (tid < 128) s_wsc[tid] = Wsc[tid];
    if (tid < 65)  s_coff[tid] = g_csr_off[b*65 + tid];
    if (tid < 128)       s_gv[tid] = g_gve[b*128 + tid];
    else if (tid < 256)  s_gv[tid] = g_gvn[b*128 + (tid-128)];
    else if (tid < 384)  s_gv[tid] = g_gve[(8 + b)*128 + (tid-256)];

    // h0 = lrelu(A + C + sp*w3 + bias) -> fp16
    #pragma unroll
    for (int i = tid; i < 2048; i += 512){
        int row = i >> 5, c4 = i & 31;
        float sp = spdist[(b*64 + d)*64 + row];
        float4 a  = *(const float4*)&g_A[(b*64 + row)*128 + c4*4];
        float4 cc = *(const float4*)&g_C[bd*128 + c4*4];
        float4 w  = *(const float4*)&w3[c4*4];
        float4 bi = *(const float4*)&bias[c4*4];
        union { uint2 u; __half2 h[2]; } pk;
        pk.h[0] = __floats2half2_rn(lrelu(a.x + cc.x + sp*w.x + bi.x),
                                    lrelu(a.y + cc.y + sp*w.y + bi.y));
        pk.h[1] = __floats2half2_rn(lrelu(a.z + cc.z + sp*w.z + bi.z),
                                    lrelu(a.w + cc.w + sp*w.w + bi.w));
        *(uint2*)&s_h[row*PH + c4*4] = pk.u;
    }

    // fragment addresses
    int l15 = lane & 15, kA = ((lane>>4)&1)*8, kB = ((lane>>3)&1)*8;
    uint32_t aAe[2][2], aAh[2], aAg[2], aBe[2], aBs, aBs2;
    #pragma unroll
    for (int m = 0; m < 2; m++){
        uint32_t ro = (uint32_t)(((wr + m*16 + l15)*PH + kA))*2u;
        aAe[0][m] = sb + OB_EE + ro;
        aAe[1][m] = sb + OB_EE + 34816u + ro;
        aAh[m] = sb + OB_H  + (uint32_t)(((wr2 + m*16 + l15)*PH + kA))*2u;
        aAg[m] = sb + OB_HS + (uint32_t)(((wr2 + m*16 + l15)*PH + kA))*2u;
    }
    #pragma unroll
    for (int p = 0; p < 2; p++){
        int rn = wn + p*16 + ((lane>>4)<<3) + (lane&7);
        aBe[p] = sb + OB_W + (uint32_t)((rn*PH + kB))*2u;
    }
    {
        int rn = wn2 + ((lane>>4)<<3) + (lane&7);
        aBs  = sb + OB_W  + (uint32_t)((rn*PH + kB))*2u;
        aBs2 = sb + OB_W2 + (uint32_t)((rn*PH + kB))*2u;
    }

    for (int s = 0; s < 2; s++){
        const __half* Wb = g_Wh + (1 + s*5)*16384;
        int gvo = s*256;
        if (s == 0) CPA_WAIT0();                 // Ws0/Wd0/ee landed
        __syncthreads();

        // ---- hs/hd dual gemm (shared A frags), fp16 stores ----
        {
            float ch[2][2][4] = {}, cd[2][2][4] = {};
            g64h_dual(ch, cd, aAh, aBs, aBs2);
            #pragma unroll
            for (int m = 0; m < 2; m++){
                int rA = wr2 + m*16 + trow;
                #pragma unroll
                for (int nt = 0; nt < 2; nt++){
                    int col = wn2 + nt*8 + tcol2;
                    *(__half2*)&s_hs[rA*PH + col]     = __floats2half2_rn(ch[m][nt][0], ch[m][nt][1]);
                    *(__half2*)&s_hs[(rA+8)*PH + col] = __floats2half2_rn(ch[m][nt][2], ch[m][nt][3]);
                    *(__half2*)&s_hd[rA*PH + col]     = __floats2half2_rn(cd[m][nt][0], cd[m][nt][1]);
                    *(__half2*)&s_hd[(rA+8)*PH + col] = __floats2half2_rn(cd[m][nt][2], cd[m][nt][3]);
                }
            }
        }
        __syncthreads();                         // hs/hd visible; s_w/s_w2 reads done
        copy_hh<512>(s_w, Wb, tid);              // Wedge
        if (s == 0) copy_hh<512>(s_w2, Wb + 3*16384, tid);   // Wn1
        __syncthreads();

        // ---- edge tiles ----
        for (int et = 0; et < 2; et++){
            int e0 = et*128;
            float c8[2][4][4] = {};
            g128h(c8, aAe[et], aBe);
            if (s == 0){
                __syncthreads();                 // A-reads done before in-place write
                #pragma unroll
                for (int m = 0; m < 2; m++){
                    int lrA = wr + m*16 + trow, lrB = lrA + 8;
                    int sA = s_src[e0+lrA], dA = s_dst[e0+lrA];
                    int sB = s_src[e0+lrB], dB = s_dst[e0+lrB];
                    #pragma unroll
                    for (int nt = 0; nt < 4; nt++){
                        int col = wn + nt*8 + tcol2;
                        float2 gv = *(float2*)&s_gv[gvo + col];
                        float2 h1 = __half22float2(*(__half2*)&s_hs[sA*PH + col]);
                        float2 d1 = __half22float2(*(__half2*)&s_hd[dA*PH + col]);
                        float2 p1 = __half22float2(*(__half2*)&s_ee[(e0+lrA)*PH + col]);
                        *(__half2*)&s_ee[(e0+lrA)*PH + col] = __floats2half2_rn(
                            p1.x + lrelu(c8[m][nt][0] + h1.x + d1.x + gv.x),
                            p1.y + lrelu(c8[m][nt][1] + h1.y + d1.y + gv.y));
                        float2 h2 = __half22float2(*(__half2*)&s_hs[sB*PH + col]);
                        float2 d2 = __half22float2(*(__half2*)&s_hd[dB*PH + col]);
                        float2 p2 = __half22float2(*(__half2*)&s_ee[(e0+lrB)*PH + col]);
                        *(__half2*)&s_ee[(e0+lrB)*PH + col] = __floats2half2_rn(
                            p2.x + lrelu(c8[m][nt][2] + h2.x + d2.x + gv.x),
                            p2.y + lrelu(c8[m][nt][3] + h2.y + d2.y + gv.y));
                    }
                }
            } else {
                float part[2][2] = {{0.f,0.f},{0.f,0.f}};
                #pragma unroll
                for (int m = 0; m < 2; m++){
                    int lrA = wr + m*16 + trow, lrB = lrA + 8;
                    int sA = s_src[e0+lrA], dA = s_dst[e0+lrA];
                    int sB = s_src[e0+lrB], dB = s_dst[e0+lrB];
                    #pragma unroll
                    for (int nt = 0; nt < 4; nt++){
                        int col = wn + nt*8 + tcol2;
                        float2 gv = *(float2*)&s_gv[gvo + col];
                        float2 wv = *(float2*)&s_wsc[col];
                        float2 h1 = __half22float2(*(__half2*)&s_hs[sA*PH + col]);
                        float2 d1 = __half22float2(*(__half2*)&s_hd[dA*PH + col]);
                        float2 p1 = __half22float2(*(__half2*)&s_ee[(e0+lrA)*PH + col]);
                        float o1x = p1.x + lrelu(c8[m][nt][0] + h1.x + d1.x + gv.x);
                        float o1y = p1.y + lrelu(c8[m][nt][1] + h1.y + d1.y + gv.y);
                        part[m][0] += o1x*wv.x + o1y*wv.y;
                        float2 h2 = __half22float2(*(__half2*)&s_hs[sB*PH + col]);
                        float2 d2 = __half22float2(*(__half2*)&s_hd[dB*PH + col]);
                        float2 p2 = __half22float2(*(__half2*)&s_ee[(e0+lrB)*PH + col]);
                        float o2x = p2.x + lrelu(c8[m][nt][2] + h2.x + d2.x + gv.x);
                        float o2y = p2.y + lrelu(c8[m][nt][3] + h2.y + d2.y + gv.y);
                        part[m][1] += o2x*wv.x + o2y*wv.y;
                    }
                }
                #pragma unroll
                for (int m = 0; m < 2; m++)
                    #pragma unroll
                    for (int i = 0; i < 2; i++){
                        float v = part[m][i];
                        v += __shfl_xor_sync(0xFFFFFFFFu, v, 1);
                        v += __shfl_xor_sync(0xFFFFFFFFu, v, 2);
                        if ((lane & 3) == 0)
                            atomicAdd(&s_sc[e0 + wr + m*16 + trow + i*8], v);
                    }
            }
        }
        __syncthreads();

        if (s == 0){
            // ---- agg (uint4 loads) -> s_ag ; Wn2 -> s_w ----
            {
                int n = tid >> 3, cg = tid & 7;
                float acc[16];
                #pragma unroll
                for (int q = 0; q < 16; q++) acc[q] = 0.f;
                int j0 = s_coff[n], j1 = s_coff[n+1];
                for (int j = j0; j < j1; j++){
                    const uint4* p = (const uint4*)&s_ee[s_cedge[j]*PH + cg*16];
                    uint4 v0 = p[0], v1 = p[1];
                    const __half2* h0 = (const __half2*)&v0;
                    const __half2* h1 = (const __half2*)&v1;
                    #pragma unroll
                    for (int q = 0; q < 4; q++){
                        float2 a0 = __half22float2(h0[q]);
                        float2 a1 = __half22float2(h1[q]);
                        acc[2*q]   += a0.x; acc[2*q+1] += a0.y;
                        acc[8+2*q] += a1.x; acc[8+2*q+1] += a1.y;
                    }
                }
                union { uint4 u[2]; __half2 h[8]; } pk;
                #pragma unroll
                for (int q = 0; q < 8; q++) pk.h[q] = __floats2half2_rn(acc[2*q], acc[2*q+1]);
                *(uint4*)&s_ag[n*PH + cg*16]     = pk.u[0];
                *(uint4*)&s_ag[n*PH + cg*16 + 8] = pk.u[1];
            }
            copy_hh<512>(s_w, Wb + 4*16384, tid);      // Wn2
            __syncthreads();

            float cn[2][2][4] = {};
            g64h(cn, aAh, aBs2);                 // h @ Wn1 (s_w2)
            g64h(cn, aAg, aBs);                  // agg @ Wn2 (s_w)
            __syncthreads();
            #pragma unroll
            for (int m = 0; m < 2; m++){
                int rA = wr2 + m*16 + trow;
                #pragma unroll
                for (int nt = 0; nt < 2; nt++){
                    int col = wn2 + nt*8 + tcol2;
                    float2 gv = *(float2*)&s_gv[128 + col];
                    float2 h1 = __half22float2(*(__half2*)&s_h[rA*PH + col]);
                    float2 h2 = __half22float2(*(__half2*)&s_h[(rA+8)*PH + col]);
                    *(__half2*)&s_h[rA*PH + col] = __floats2half2_rn(
                        h1.x + lrelu(cn[m][nt][0] + gv.x),
                        h1.y + lrelu(cn[m][nt][1] + gv.y));
                    *(__half2*)&s_h[(rA+8)*PH + col] = __floats2half2_rn(
                        h2.x + lrelu(cn[m][nt][2] + gv.x),
                        h2.y + lrelu(cn[m][nt][3] + gv.y));
                }
            }
            __syncthreads();
            copy_hh<512>(s_w,  g_Wh + 7*16384, tid);   // Ws (s1)
            copy_hh<512>(s_w2, g_Wh + 8*16384, tid);   // Wd (s1)
        } else {
            if (tid < 256)
                out[b*(E_*N_) + tid*N_ + d] = s_sc[tid];
        }
    }
}

// ---------------- launch ----------------
extern "C" void kernel_launch(void* const* d_in, const int* in_sizes, int n_in,
                              void* d_out, int out_size){
    const float* x          = (const float*)d_in[0];
    const float* edge_attr  = (const float*)d_in[1];
    const float* u          = (const float*)d_in[2];
    const float* spdist     = (const float*)d_in[3];
    const int*   edge_index = (const int*)  d_in[4];
    const float* W_node_enc = (const float*)d_in[5];
    const float* b_node_enc = (const float*)d_in[6];
    const float* W_edge_enc = (const float*)d_in[7];
    const float* b_edge_enc = (const float*)d_in[8];
    const float* W_glob_enc = (const float*)d_in[9];
    const float* b_glob_enc = (const float*)d_in[10];
    const float* W_edge_upd = (const float*)d_in[11];
    const float* b_edge_upd = (const float*)d_in[12];
    const float* W_node_upd = (const float*)d_in[13];
    const float* b_node_upd = (const float*)d_in[14];
    const float* W_score    = (const float*)d_in[15];
    const float* b_score    = (const float*)d_in[16];
    float* out = (float*)d_out;

    cudaFuncSetAttribute(k_prep,  cudaFuncAttributeMaxDynamicSharedMemorySize, SMEM_PREP);
    cudaFuncSetAttribute(k_fused, cudaFuncAttributeMaxDynamicSharedMemorySize, SMEM_FUSED);

    k_prep <<<142, 512, SMEM_PREP>>>(x, W_node_enc, u, W_glob_enc, b_glob_enc,
                                     W_edge_enc, b_edge_enc, edge_attr,
                                     W_edge_upd, b_edge_upd, W_node_upd, b_node_upd,
                                     edge_index);
    k_fused<<<512, 512, SMEM_FUSED>>>(spdist, edge_index,
                                      W_node_enc + 256*128, b_node_enc,
                                      W_score, b_score, out);
}

// round 17
// speedup vs baseline: 1.0456x; 1.0429x over previous
#include <cuda_runtime.h>
#include <cuda_fp16.h>
#include <cstdint>

#define B_   8
#define N_   64
#define E_   256
#define L_   128
#define PH    136      // half pitch for MMA operand tiles

// ---------------- device globals ----------------
__device__ float  g_A[512*128];
__device__ float  g_C[512*128];
__device__ __half g_eenc[2048*128];
__device__ float  g_gve[2*8*128];
__device__ float  g_gvn[2*8*128];
__device__ __half g_Wh[11*128*128];       // pre-transposed [n][k] fp16 weights
__device__ int    g_csr_off[8*65];
__device__ int    g_csr_edge[8*256];

__device__ __forceinline__ float lrelu(float v){ return v > 0.f ? v : 0.01f*v; }
__device__ __forceinline__ uint32_t smem_u32(const void* p){
    uint32_t a;
    asm("{ .reg .u64 t; cvta.to.shared.u64 t, %1; cvt.u32.u64 %0, t; }" : "=r"(a) : "l"(p));
    return a;
}

#define LDSM4(D, addr) \
    asm volatile("ldmatrix.sync.aligned.m8n8.x4.shared.b16 {%0,%1,%2,%3}, [%4];" \
        : "=r"((D)[0]),"=r"((D)[1]),"=r"((D)[2]),"=r"((D)[3]) : "r"(addr))

#define MMA_H(C, A, b0, b1) \
    asm volatile("mma.sync.aligned.m16n8k16.row.col.f32.f16.f16.f32 " \
        "{%0,%1,%2,%3}, {%4,%5,%6,%7}, {%8,%9}, {%0,%1,%2,%3};" \
        : "+f"((C)[0]),"+f"((C)[1]),"+f"((C)[2]),"+f"((C)[3]) \
        : "r"((A)[0]),"r"((A)[1]),"r"((A)[2]),"r"((A)[3]), "r"(b0),"r"(b1))

// ---------------- tile copies ----------------
template<int NT>
__device__ __forceinline__ void copy_hh(__half* dst, const __half* __restrict__ src, int tid){
    #pragma unroll
    for (int i = tid; i < 2048; i += NT){
        int r = i >> 4, c = i & 15;
        *(uint4*)&dst[r*PH + c*8] = *(const uint4*)&src[r*128 + c*8];
    }
}
template<int NT>
__device__ __forceinline__ void copy_f2h(__half* dst, const float* __restrict__ src, int tid){
    #pragma unroll
    for (int i = tid; i < 2048; i += NT){
        int r = i >> 4, c = i & 15;
        float4 v0 = *(const float4*)&src[r*128 + c*8];
        float4 v1 = *(const float4*)&src[r*128 + c*8 + 4];
        union { uint4 u; __half2 h[4]; } pk;
        pk.h[0] = __floats2half2_rn(v0.x, v0.y);
        pk.h[1] = __floats2half2_rn(v0.z, v0.w);
        pk.h[2] = __floats2half2_rn(v1.x, v1.y);
        pk.h[3] = __floats2half2_rn(v1.z, v1.w);
        *(uint4*)&dst[r*PH + c*8] = pk.u;
    }
}

// ---------------- gemm cores ----------------
__device__ __forceinline__ void g128h(float c[2][4][4], const uint32_t aA[2], const uint32_t aB[2]){
    #pragma unroll
    for (int k = 0; k < 8; k++){
        uint32_t A0[4], A1[4];
        LDSM4(A0, aA[0] + (uint32_t)k*32u);
        LDSM4(A1, aA[1] + (uint32_t)k*32u);
        #pragma unroll
        for (int p = 0; p < 2; p++){
            uint32_t Bv[4];
            LDSM4(Bv, aB[p] + (uint32_t)k*32u);
            MMA_H(c[0][2*p],   A0, Bv[0], Bv[1]);
            MMA_H(c[0][2*p+1], A0, Bv[2], Bv[3]);
            MMA_H(c[1][2*p],   A1, Bv[0], Bv[1]);
            MMA_H(c[1][2*p+1], A1, Bv[2], Bv[3]);
        }
    }
}
__device__ __forceinline__ void g64h(float c[2][2][4], const uint32_t aA[2], uint32_t aB){
    #pragma unroll
    for (int k = 0; k < 8; k++){
        uint32_t A0[4], A1[4], Bv[4];
        LDSM4(A0, aA[0] + (uint32_t)k*32u);
        LDSM4(A1, aA[1] + (uint32_t)k*32u);
        LDSM4(Bv, aB + (uint32_t)k*32u);
        MMA_H(c[0][0], A0, Bv[0], Bv[1]);
        MMA_H(c[0][1], A0, Bv[2], Bv[3]);
        MMA_H(c[1][0], A1, Bv[0], Bv[1]);
        MMA_H(c[1][1], A1, Bv[2], Bv[3]);
    }
}
__device__ __forceinline__ void g64h_dual(float ch[2][2][4], float cd[2][2][4],
                                          const uint32_t aA[2], uint32_t aB, uint32_t aB2){
    #pragma unroll
    for (int k = 0; k < 8; k++){
        uint32_t A0[4], A1[4], Bv[4], Bw[4];
        LDSM4(A0, aA[0] + (uint32_t)k*32u);
        LDSM4(A1, aA[1] + (uint32_t)k*32u);
        LDSM4(Bv, aB + (uint32_t)k*32u);
        LDSM4(Bw, aB2 + (uint32_t)k*32u);
        MMA_H(ch[0][0], A0, Bv[0], Bv[1]);
        MMA_H(ch[0][1], A0, Bv[2], Bv[3]);
        MMA_H(ch[1][0], A1, Bv[0], Bv[1]);
        MMA_H(ch[1][1], A1, Bv[2], Bv[3]);
        MMA_H(cd[0][0], A0, Bw[0], Bw[1]);
        MMA_H(cd[0][1], A0, Bw[2], Bw[3]);
        MMA_H(cd[1][0], A1, Bw[0], Bw[1]);
        MMA_H(cd[1][1], A1, Bw[2], Bw[3]);
    }
}

// ---------------- merged prep kernel (512 threads, from R16) ----------------
#define SMEM_PREP (34816*2)
__global__ __launch_bounds__(512, 1) void k_prep(
                       const float* __restrict__ x, const float* __restrict__ Wne,
                       const float* __restrict__ u, const float* __restrict__ Wg,
                       const float* __restrict__ bg,
                       const float* __restrict__ Wenc, const float* __restrict__ benc,
                       const float* __restrict__ ea,
                       const float* __restrict__ Wedge, const float* __restrict__ be,
                       const float* __restrict__ Wnode, const float* __restrict__ bn,
                       const int* __restrict__ edge_index){
    __shared__ float sbuf[64*129];
    extern __shared__ char dyn[];
    int blk = blockIdx.x, tid = threadIdx.x;
    if (blk < 22){
        int mat = blk >> 1, k0 = (blk & 1)*64;
        int m = mat - 1, s = m / 5, t = m % 5;
        #pragma unroll
        for (int i = tid; i < 8192; i += 512){
            int kk = i >> 7, n = i & 127;
            int k = k0 + kk;
            float v;
            if (mat == 0) v = Wenc[k*L_ + n];
            else if (t == 0) v = Wedge[(s*512 +       k)*L_ + n];
            else if (t == 1) v = Wedge[(s*512 + 128 + k)*L_ + n];
            else if (t == 2) v = Wedge[(s*512 + 256 + k)*L_ + n];
            else if (t == 3) v = Wnode[(s*384 +       k)*L_ + n];
            else             v = Wnode[(s*384 + 128 + k)*L_ + n];
            sbuf[kk*129 + n] = v;
        }
        __syncthreads();
        #pragma unroll
        for (int j = tid; j < 8192; j += 512){
            int n = j >> 6, kk = j & 63;
            g_Wh[mat*16384 + n*128 + k0 + kk] = __float2half_rn(sbuf[kk*129 + n]);
        }
    } else if (blk < 86){
        float (*xs)[128] = (float(*)[128])sbuf;
        const float* W1 = Wne;
        const float* W2 = Wne + 16384;
        int r0 = (blk - 22)*8;
        for (int i = tid; i < 1024; i += 512) xs[i>>7][i&127] = x[(r0 + (i>>7))*128 + (i&127)];
        __syncthreads();
        int c = tid & 127, rq = tid >> 7;
        float a1[2] = {0,0}, a2[2] = {0,0};
        #pragma unroll 8
        for (int k = 0; k < 128; k++){
            float w1 = W1[k*128 + c], w2 = W2[k*128 + c];
            #pragma unroll
            for (int j = 0; j < 2; j++){
                float xv = xs[rq*2 + j][k];
                a1[j] += xv*w1; a2[j] += xv*w2;
            }
        }
        #pragma unroll
        for (int j = 0; j < 2; j++){
            g_A[(r0 + rq*2 + j)*128 + c] = a1[j];
            g_C[(r0 + rq*2 + j)*128 + c] = a2[j];
        }
    } else if (blk < 94){
        int* cnt = (int*)sbuf;
        int* off = cnt + 64;
        int b = blk - 86;
        if (tid < 64) cnt[tid] = 0;
        __syncthreads();
        int dv = -1;
        if (tid < 256){
            dv = edge_index[b*512 + 256 + tid];
            atomicAdd(&cnt[dv], 1);
        }
        __syncthreads();
        if (tid == 0){
            int o = 0;
            for (int n = 0; n < 64; n++){ off[n] = o; o += cnt[n]; }
            off[64] = o;
            for (int n = 0; n <= 64; n++) g_csr_off[b*65 + n] = off[n];
            for (int n = 0; n < 64; n++) cnt[n] = off[n];
        }
        __syncthreads();
        if (tid < 256){
            int pos = atomicAdd(&cnt[dv], 1);
            g_csr_edge[b*256 + pos] = tid;
        }
    } else if (blk < 126){
        float* red = sbuf;
        float* sgg = sbuf + 256;
        int id = blk - 94;
        int b = id & 7, s = (id >> 3) & 1, kind = id >> 4;
        int c = tid & 127, hf = (tid >> 7) & 1;
        if (tid < 256){
            float p = 0.f;
            #pragma unroll 16
            for (int k = 0; k < 64; k++)
                p += u[b*128 + hf*64 + k] * Wg[(hf*64 + k)*128 + c];
            red[tid] = p;
        }
        __syncthreads();
        if (tid < 128) sgg[tid] = lrelu(bg[tid] + red[tid] + red[tid + 128]);
        __syncthreads();
        if (tid < 256){
            const float* W = (kind == 0) ? (Wedge + (s*512 + 384)*L_)
                                         : (Wnode + (s*384 + 256)*L_);
            float q = 0.f;
            #pragma unroll 16
            for (int k = 0; k < 64; k++)
                q += sgg[hf*64 + k] * W[(hf*64 + k)*128 + c];
            red[tid] = q;
        }
        __syncthreads();
        if (tid < 128){
            float acc = ((kind == 0) ? be[s*128 + tid] : bn[s*128 + tid])
                      + red[tid] + red[tid + 128];
            if (kind == 0) g_gve[(s*8 + b)*128 + tid] = acc;
            else           g_gvn[(s*8 + b)*128 + tid] = acc;
        }
    } else {
        // edge encoder block: 16 warps, 128x128 gemm
        __half* s_xh = (__half*)dyn;
        __half* s_wh = (__half*)(dyn + 34816);
        int eb = blk - 126;
        int row0 = eb*128;
        int wid = tid >> 5, lane = tid & 31;
        int trow = lane >> 2, tcol2 = (lane & 3)*2;
        int wr = (wid & 3)*32, wn = (wid >> 2)*32;

        copy_f2h<512>(s_xh, ea + (long)row0*128, tid);
        #pragma unroll
        for (int i = tid; i < 16384; i += 512){
            int k = i >> 7, n = i & 127;
            s_wh[n*PH + k] = __float2half_rn(Wenc[k*128 + n]);
        }
        __syncthreads();

        uint32_t sb = smem_u32(dyn);
        int l15 = lane & 15, kA = ((lane>>4)&1)*8, kB = ((lane>>3)&1)*8;
        uint32_t aA[2], aB[2];
        #pragma unroll
        for (int m = 0; m < 2; m++)
            aA[m] = sb + (uint32_t)(((wr + m*16 + l15)*PH + kA))*2u;
        #pragma unroll
        for (int p = 0; p < 2; p++){
            int rn = wn + p*16 + ((lane>>4)<<3) + (lane&7);
            aB[p] = sb + 34816u + (uint32_t)((rn*PH + kB))*2u;
        }
        float c8[2][4][4] = {};
        g128h(c8, aA, aB);

        #pragma unroll
        for (int m = 0; m < 2; m++){
            int rA = row0 + wr + m*16 + trow;
            #pragma unroll
            for (int nt = 0; nt < 4; nt++){
                int col = wn + nt*8 + tcol2;
                float2 bi = *(const float2*)&benc[col];
                *(__half2*)&g_eenc[(long)rA*128 + col] =
                    __floats2half2_rn(lrelu(c8[m][nt][0]+bi.x), lrelu(c8[m][nt][1]+bi.y));
                *(__half2*)&g_eenc[(long)(rA+8)*128 + col] =
                    __floats2half2_rn(lrelu(c8[m][nt][2]+bi.x), lrelu(c8[m][nt][3]+bi.y));
            }
        }
    }
}

// ---------------- fused per-(b,d) kernel (R11 verbatim) ----------------
#define OB_EE  0         // 69632
#define OB_W   69632     // 34816
#define OB_W2  104448    // 34816
#define OB_H   139264    // 17408
#define OB_HS  156672    // 17408 (s_ag aliases; hs dead by agg time)
#define OB_HD  174080    // 17408
#define OB_GV  191488    // 2048
#define OB_WSC 193536    // 512
#define OB_SC  194048    // 1024
#define OB_INT 195072    // 3336
#define SMEM_FUSED 198408

__global__ __launch_bounds__(512, 1) void k_fused(
    const float* __restrict__ spdist, const int* __restrict__ edge_index,
    const float* __restrict__ w3, const float* __restrict__ bias,
    const float* __restrict__ Wsc, const float* __restrict__ bsc,
    float* __restrict__ out)
{
    extern __shared__ char smc[];
    __half* s_ee  = (__half*)(smc + OB_EE);
    __half* s_h   = (__half*)(smc + OB_H);
    __half* s_hs  = (__half*)(smc + OB_HS);
    __half* s_hd  = (__half*)(smc + OB_HD);
    __half* s_ag  = (__half*)(smc + OB_HS);
    float*  s_gv  = (float*)(smc + OB_GV);
    float*  s_wsc = (float*)(smc + OB_WSC);
    float*  s_sc  = (float*)(smc + OB_SC);
    int*    s_src = (int*)(smc + OB_INT);
    int*    s_dst = s_src + 256;
    int*    s_coff = s_dst + 256;
    int*    s_cedge = s_coff + 66;
    __half* s_w   = (__half*)(smc + OB_W);
    __half* s_w2  = (__half*)(smc + OB_W2);

    int tid = threadIdx.x, wid = tid >> 5, lane = tid & 31;
    int bd = blockIdx.x, b = bd >> 6, d = bd & 63;
    int trow = lane >> 2, tcol2 = (lane & 3)*2;
    int wr  = (wid & 3)*32, wn  = (wid >> 2)*32;
    int wr2 = (wid & 1)*32, wn2 = (wid >> 1)*16;

    // ---- init ----
    if (tid < 256){
        s_src[tid] = edge_index[b*512 + tid];
        s_dst[tid] = edge_index[b*512 + 256 + tid];
        s_cedge[tid] = g_csr_edge[b*256 + tid];
        s_sc[tid] = bsc[0];
    }
    if (tid < 128) s_wsc[tid] = Wsc[tid];
    if (tid < 65)  s_coff[tid] = g_csr_off[b*65 + tid];
    if (tid < 128)       s_gv[tid] = g_gve[b*128 + tid];
    else if (tid < 256)  s_gv[tid] = g_gvn[b*128 + (tid-128)];
    else if (tid < 384)  s_gv[tid] = g_gve[(8 + b)*128 + (tid-256)];

    // ee tiles <- g_eenc
    #pragma unroll
    for (int i = tid; i < 4096; i += 512){
        int r = i >> 4, c = i & 15;
        *(uint4*)&s_ee[r*PH + c*8] = *(const uint4*)&g_eenc[((long)b*256 + r)*128 + c*8];
    }
    // h0 = lrelu(A + C + sp*w3 + bias) -> fp16
    #pragma unroll
    for (int i = tid; i < 2048; i += 512){
        int row = i >> 5, c4 = i & 31;
        float sp = spdist[(b*64 + d)*64 + row];
        float4 a  = *(const float4*)&g_A[(b*64 + row)*128 + c4*4];
        float4 cc = *(const float4*)&g_C[bd*128 + c4*4];
        float4 w  = *(const float4*)&w3[c4*4];
        float4 bi = *(const float4*)&bias[c4*4];
        union { uint2 u; __half2 h[2]; } pk;
        pk.h[0] = __floats2half2_rn(lrelu(a.x + cc.x + sp*w.x + bi.x),
                                    lrelu(a.y + cc.y + sp*w.y + bi.y));
        pk.h[1] = __floats2half2_rn(lrelu(a.z + cc.z + sp*w.z + bi.z),
                                    lrelu(a.w + cc.w + sp*w.w + bi.w));
        *(uint2*)&s_h[row*PH + c4*4] = pk.u;
    }

    // fragment addresses
    uint32_t sb = smem_u32(smc);
    int l15 = lane & 15, kA = ((lane>>4)&1)*8, kB = ((lane>>3)&1)*8;
    uint32_t aAe[2][2], aAh[2], aAg[2], aBe[2], aBs, aBs2;
    #pragma unroll
    for (int m = 0; m < 2; m++){
        uint32_t ro = (uint32_t)(((wr + m*16 + l15)*PH + kA))*2u;
        aAe[0][m] = sb + OB_EE + ro;
        aAe[1][m] = sb + OB_EE + 34816u + ro;
        aAh[m] = sb + OB_H  + (uint32_t)(((wr2 + m*16 + l15)*PH + kA))*2u;
        aAg[m] = sb + OB_HS + (uint32_t)(((wr2 + m*16 + l15)*PH + kA))*2u;
    }
    #pragma unroll
    for (int p = 0; p < 2; p++){
        int rn = wn + p*16 + ((lane>>4)<<3) + (lane&7);
        aBe[p] = sb + OB_W + (uint32_t)((rn*PH + kB))*2u;
    }
    {
        int rn = wn2 + ((lane>>4)<<3) + (lane&7);
        aBs  = sb + OB_W  + (uint32_t)((rn*PH + kB))*2u;
        aBs2 = sb + OB_W2 + (uint32_t)((rn*PH + kB))*2u;
    }

    for (int s = 0; s < 2; s++){
        const __half* Wb = g_Wh + (1 + s*5)*16384;
        int gvo = s*256;
        if (s == 0){
            copy_hh<512>(s_w,  Wb + 1*16384, tid);    // Ws
            copy_hh<512>(s_w2, Wb + 2*16384, tid);    // Wd
        }
        __syncthreads();

        // ---- hs/hd dual gemm (shared A frags), fp16 stores ----
        {
            float ch[2][2][4] = {}, cd[2][2][4] = {};
            g64h_dual(ch, cd, aAh, aBs, aBs2);
            #pragma unroll
            for (int m = 0; m < 2; m++){
                int rA = wr2 + m*16 + trow;
                #pragma unroll
                for (int nt = 0; nt < 2; nt++){
                    int col = wn2 + nt*8 + tcol2;
                    *(__half2*)&s_hs[rA*PH + col]     = __floats2half2_rn(ch[m][nt][0], ch[m][nt][1]);
                    *(__half2*)&s_hs[(rA+8)*PH + col] = __floats2half2_rn(ch[m][nt][2], ch[m][nt][3]);
                    *(__half2*)&s_hd[rA*PH + col]     = __floats2half2_rn(cd[m][nt][0], cd[m][nt][1]);
                    *(__half2*)&s_hd[(rA+8)*PH + col] = __floats2half2_rn(cd[m][nt][2], cd[m][nt][3]);
                }
            }
        }
        __syncthreads();                         // hs/hd visible; s_w/s_w2 reads done
        copy_hh<512>(s_w, Wb, tid);              // Wedge
        if (s == 0) copy_hh<512>(s_w2, Wb + 3*16384, tid);   // Wn1
        __syncthreads();

        // ---- edge tiles ----
        for (int et = 0; et < 2; et++){
            int e0 = et*128;
            float c8[2][4][4] = {};
            g128h(c8, aAe[et], aBe);
            if (s == 0){
                __syncthreads();                 // A-reads done before in-place write
                #pragma unroll
                for (int m = 0; m < 2; m++){
                    int lrA = wr + m*16 + trow, lrB = lrA + 8;
                    int sA = s_src[e0+lrA], dA = s_dst[e0+lrA];
                    int sB = s_src[e0+lrB], dB = s_dst[e0+lrB];
                    #pragma unroll
                    for (int nt = 0; nt < 4; nt++){
                        int col = wn + nt*8 + tcol2;
                        float2 gv = *(float2*)&s_gv[gvo + col];
                        float2 h1 = __half22float2(*(__half2*)&s_hs[sA*PH + col]);
                        float2 d1 = __half22float2(*(__half2*)&s_hd[dA*PH + col]);
                        float2 p1 = __half22float2(*(__half2*)&s_ee[(e0+lrA)*PH + col]);
                        *(__half2*)&s_ee[(e0+lrA)*PH + col] = __floats2half2_rn(
                            p1.x + lrelu(c8[m][nt][0] + h1.x + d1.x + gv.x),
                            p1.y + lrelu(c8[m][nt][1] + h1.y + d1.y + gv.y));
                        float2 h2 = __half22float2(*(__half2*)&s_hs[sB*PH + col]);
                        float2 d2 = __half22float2(*(__half2*)&s_hd[dB*PH + col]);
                        float2 p2 = __half22float2(*(__half2*)&s_ee[(e0+lrB)*PH + col]);
                        *(__half2*)&s_ee[(e0+lrB)*PH + col] = __floats2half2_rn(
                            p2.x + lrelu(c8[m][nt][2] + h2.x + d2.x + gv.x),
                            p2.y + lrelu(c8[m][nt][3] + h2.y + d2.y + gv.y));
                    }
                }
            } else {
                float part[2][2] = {{0.f,0.f},{0.f,0.f}};
                #pragma unroll
                for (int m = 0; m < 2; m++){
                    int lrA = wr + m*16 + trow, lrB = lrA + 8;
                    int sA = s_src[e0+lrA], dA = s_dst[e0+lrA];
                    int sB = s_src[e0+lrB], dB = s_dst[e0+lrB];
                    #pragma unroll
                    for (int nt = 0; nt < 4; nt++){
                        int col = wn + nt*8 + tcol2;
                        float2 gv = *(float2*)&s_gv[gvo + col];
                        float2 wv = *(float2*)&s_wsc[col];
                        float2 h1 = __half22float2(*(__half2*)&s_hs[sA*PH + col]);
                        float2 d1 = __half22float2(*(__half2*)&s_hd[dA*PH + col]);
                        float2 p1 = __half22float2(*(__half2*)&s_ee[(e0+lrA)*PH + col]);
                        float o1x = p1.x + lrelu(c8[m][nt][0] + h1.x + d1.x + gv.x);
                        float o1y = p1.y + lrelu(c8[m][nt][1] + h1.y + d1.y + gv.y);
                        part[m][0] += o1x*wv.x + o1y*wv.y;
                        float2 h2 = __half22float2(*(__half2*)&s_hs[sB*PH + col]);
                        float2 d2 = __half22float2(*(__half2*)&s_hd[dB*PH + col]);
                        float2 p2 = __half22float2(*(__half2*)&s_ee[(e0+lrB)*PH + col]);
                        float o2x = p2.x + lrelu(c8[m][nt][2] + h2.x + d2.x + gv.x);
                        float o2y = p2.y + lrelu(c8[m][nt][3] + h2.y + d2.y + gv.y);
                        part[m][1] += o2x*wv.x + o2y*wv.y;
                    }
                }
                #pragma unroll
                for (int m = 0; m < 2; m++)
                    #pragma unroll
                    for (int i = 0; i < 2; i++){
                        float v = part[m][i];
                        v += __shfl_xor_sync(0xFFFFFFFFu, v, 1);
                        v += __shfl_xor_sync(0xFFFFFFFFu, v, 2);
                        if ((lane & 3) == 0)
                            atomicAdd(&s_sc[e0 + wr + m*16 + trow + i*8], v);
                    }
            }
        }
        __syncthreads();

        if (s == 0){
            // ---- agg (uint4 loads) -> s_ag ; Wn2 -> s_w ----
            {
                int n = tid >> 3, cg = tid & 7;
                float acc[16];
                #pragma unroll
                for (int q = 0; q < 16; q++) acc[q] = 0.f;
                int j0 = s_coff[n], j1 = s_coff[n+1];
                for (int j = j0; j < j1; j++){
                    const uint4* p = (const uint4*)&s_ee[s_cedge[j]*PH + cg*16];
                    uint4 v0 = p[0], v1 = p[1];
                    const __half2* h0 = (const __half2*)&v0;
                    const __half2* h1 = (const __half2*)&v1;
                    #pragma unroll
                    for (int q = 0; q < 4; q++){
                        float2 a0 = __half22float2(h0[q]);
                        float2 a1 = __half22float2(h1[q]);
                        acc[2*q]   += a0.x; acc[2*q+1] += a0.y;
                        acc[8+2*q] += a1.x; acc[8+2*q+1] += a1.y;
                    }
                }
                union { uint4 u[2]; __half2 h[8]; } pk;
                #pragma unroll
                for (int q = 0; q < 8; q++) pk.h[q] = __floats2half2_rn(acc[2*q], acc[2*q+1]);
                *(uint4*)&s_ag[n*PH + cg*16]     = pk.u[0];
                *(uint4*)&s_ag[n*PH + cg*16 + 8] = pk.u[1];
            }
            copy_hh<512>(s_w, Wb + 4*16384, tid);      // Wn2
            __syncthreads();

            float cn[2][2][4] = {};
            g64h(cn, aAh, aBs2);                 // h @ Wn1 (s_w2)
            g64h(cn, aAg, aBs);                  // agg @ Wn2 (s_w)
            __syncthreads();
            #pragma unroll
            for (int m = 0; m < 2; m++){
                int rA = wr2 + m*16 + trow;
                #pragma unroll
                for (int nt = 0; nt < 2; nt++){
                    int col = wn2 + nt*8 + tcol2;
                    float2 gv = *(float2*)&s_gv[128 + col];
                    float2 h1 = __half22float2(*(__half2*)&s_h[rA*PH + col]);
                    float2 h2 = __half22float2(*(__half2*)&s_h[(rA+8)*PH + col]);
                    *(__half2*)&s_h[rA*PH + col] = __floats2half2_rn(
                        h1.x + lrelu(cn[m][nt][0] + gv.x),
                        h1.y + lrelu(cn[m][nt][1] + gv.y));
                    *(__half2*)&s_h[(rA+8)*PH + col] = __floats2half2_rn(
                        h2.x + lrelu(cn[m][nt][2] + gv.x),
                        h2.y + lrelu(cn[m][nt][3] + gv.y));
                }
            }
            __syncthreads();
            copy_hh<512>(s_w,  g_Wh + 7*16384, tid);   // Ws (s1)
            copy_hh<512>(s_w2, g_Wh + 8*16384, tid);   // Wd (s1)
        } else {
            if (tid < 256)
                out[b*(E_*N_) + tid*N_ + d] = s_sc[tid];
        }
    }
}

// ---------------- launch ----------------
extern "C" void kernel_launch(void* const* d_in, const int* in_sizes, int n_in,
                              void* d_out, int out_size){
    const float* x          = (const float*)d_in[0];
    const float* edge_attr  = (const float*)d_in[1];
    const float* u          = (const float*)d_in[2];
    const float* spdist     = (const float*)d_in[3];
    const int*   edge_index = (const int*)  d_in[4];
    const float* W_node_enc = (const float*)d_in[5];
    const float* b_node_enc = (const float*)d_in[6];
    const float* W_edge_enc = (const float*)d_in[7];
    const float* b_edge_enc = (const float*)d_in[8];
    const float* W_glob_enc = (const float*)d_in[9];
    const float* b_glob_enc = (const float*)d_in[10];
    const float* W_edge_upd = (const float*)d_in[11];
    const float* b_edge_upd = (const float*)d_in[12];
    const float* W_node_upd = (const float*)d_in[13];
    const float* b_node_upd = (const float*)d_in[14];
    const float* W_score    = (const float*)d_in[15];
    const float* b_score    = (const float*)d_in[16];
    float* out = (float*)d_out;

    cudaFuncSetAttribute(k_prep,  cudaFuncAttributeMaxDynamicSharedMemorySize, SMEM_PREP);
    cudaFuncSetAttribute(k_fused, cudaFuncAttributeMaxDynamicSharedMemorySize, SMEM_FUSED);

    k_prep <<<142, 512, SMEM_PREP>>>(x, W_node_enc, u, W_glob_enc, b_glob_enc,
                                     W_edge_enc, b_edge_enc, edge_attr,
                                     W_edge_upd, b_edge_upd, W_node_upd, b_node_upd,
                                     edge_index);
    k_fused<<<512, 512, SMEM_FUSED>>>(spdist, edge_index,
                                      W_node_enc + 256*128, b_node_enc,
                                      W_score, b_score, out);
}